// round 1
// baseline (speedup 1.0000x reference)
#include <cuda_runtime.h>
#include <cstdint>

#define NB_B 1024
#define FAN_1 15
#define FAN_2 10
#define EMB 256
#define HID 512
#define HEADS 8
#define HD 64
#define N1 (NB_B * FAN_1)   /* 15360 */
#define N2 (N1 * FAN_2)     /* 153600 */

// ---------------- scratch (static __device__, allocation-free) ----------------
__device__ int g_seeds[NB_B];
__device__ int g_nbr1[N1];
__device__ int g_nbr2[N2];
__device__ float g_q1[(size_t)N1 * HID];
__device__ float g_s1[(size_t)N1 * HID];
__device__ float g_u1[(size_t)N1 * HEADS * EMB];
__device__ float g_m1[(size_t)N1 * HEADS * EMB];
__device__ float g_h1[(size_t)N1 * HID];
__device__ float g_q2[(size_t)NB_B * HID];
__device__ float g_s2[(size_t)NB_B * HID];
__device__ float g_u2[(size_t)NB_B * HEADS * HID];
__device__ float g_m2[(size_t)NB_B * HEADS * HID];

// ---------------- packed f32x2 helpers (B300: 2x FFMA rate) ----------------
__device__ __forceinline__ unsigned long long fma2(unsigned long long a,
                                                   unsigned long long b,
                                                   unsigned long long c) {
    unsigned long long d;
    asm("fma.rn.f32x2 %0, %1, %2, %3;" : "=l"(d) : "l"(a), "l"(b), "l"(c));
    return d;
}
__device__ __forceinline__ unsigned long long pack2(float x, float y) {
    unsigned long long r;
    asm("mov.b64 %0, {%1, %2};" : "=l"(r) : "f"(x), "f"(y));
    return r;
}
__device__ __forceinline__ unsigned long long packdup(float x) {
    unsigned long long r;
    asm("mov.b64 %0, {%1, %1};" : "=l"(r) : "f"(x));
    return r;
}
__device__ __forceinline__ void unpack2(unsigned long long v, float& x, float& y) {
    asm("mov.b64 {%0, %1}, %2;" : "=f"(x), "=f"(y) : "l"(v));
}

// ---------------- index conversion (robust to int64 vs int32 dumps) ----------------
__global__ void convert_idx(const void* sv, const void* n1v, const void* n2v) {
    const unsigned long long* p = (const unsigned long long*)sv;
    // seeds values < 500000: if buffer is int64, every high word is 0.
    // if int32, p[i] packs two indices; odd-position indices are ~never all zero.
    bool is64 = (((p[0] | p[1] | p[2] | p[3]) >> 32) == 0ULL);
    int t = blockIdx.x * blockDim.x + threadIdx.x;
    int stride = gridDim.x * blockDim.x;
    if (is64) {
        const long long* a = (const long long*)sv;
        const long long* b = (const long long*)n1v;
        const long long* c = (const long long*)n2v;
        if (t < NB_B) g_seeds[t] = (int)a[t];
        if (t < N1)   g_nbr1[t]  = (int)b[t];
        for (int i = t; i < N2; i += stride) g_nbr2[i] = (int)c[i];
    } else {
        const int* a = (const int*)sv;
        const int* b = (const int*)n1v;
        const int* c = (const int*)n2v;
        if (t < NB_B) g_seeds[t] = a[t];
        if (t < N1)   g_nbr1[t]  = b[t];
        for (int i = t; i < N2; i += stride) g_nbr2[i] = c[i];
    }
}

// ---------------- generic tiled GEMM ----------------
// C[m,n] (+= style over K):
//   BN == 0 : C = A @ B^T   (B is [N,K] row-major; contraction along B row)
//   BN == 1 : C = A @ B     (B is [K,N] row-major)
// A rows optionally gathered through idx. blockIdx.z adds (cz, az, bz, ez) offsets.
// mode 1: C = relu(acc + E) with E sharing C's layout.
// Tile: 128(M) x 64(N), KC=16, 256 threads, 8x4 micro-tile via packed f32x2.
#define KC 16

template <int BN>
__global__ __launch_bounds__(256) void gemm_kernel(
    float* __restrict__ C, int ldc, long long cz,
    const float* __restrict__ E, long long ez, int mode,
    const float* __restrict__ A, int lda, long long az,
    const int* __restrict__ idx,
    const float* __restrict__ Bm, int ldb, long long bz,
    int K)
{
    __shared__ float As[128][KC + 1];   // [m][k], stride 17 -> conflict-free
    __shared__ float Bs[KC][64 + 4];    // [k][n], stride 68 (float4-aligned)

    long long z = blockIdx.z;
    C += z * cz; A += z * az; Bm += z * bz;
    const float* Ep = (mode == 1) ? (E + z * ez) : nullptr;

    int m0 = blockIdx.y * 128;
    int n0 = blockIdx.x * 64;
    int tid = threadIdx.x;
    int kl = tid & 15;   // k within chunk (loads)
    int ml = tid >> 4;   // 0..15

    const float* arow[8];
#pragma unroll
    for (int i = 0; i < 8; i++) {
        int m = m0 + ml + i * 16;
        long long r = idx ? (long long)idx[m] : (long long)m;
        arow[i] = A + r * (long long)lda + kl;
    }
    const float* brow[4];
    int skk[4], snn[4];
#pragma unroll
    for (int i = 0; i < 4; i++) {
        if (BN == 0) {
            brow[i] = Bm + (long long)(n0 + ml + i * 16) * ldb + kl;
            skk[i] = kl; snn[i] = ml + i * 16;
        } else {
            int lin = tid + i * 256;
            int nn = lin & 63, kk = lin >> 6;
            brow[i] = Bm + (long long)kk * ldb + n0 + nn;
            skk[i] = kk; snn[i] = nn;
        }
    }

    unsigned long long acc01[8], acc23[8];
#pragma unroll
    for (int i = 0; i < 8; i++) { acc01[i] = 0ULL; acc23[i] = 0ULL; }

    int ty = tid >> 4, tx = tid & 15;

    // prefetch chunk 0
    float ra[8], rb[4];
#pragma unroll
    for (int i = 0; i < 8; i++) ra[i] = arow[i][0];
#pragma unroll
    for (int i = 0; i < 4; i++) rb[i] = brow[i][0];

    for (int k0 = 0; k0 < K; k0 += KC) {
#pragma unroll
        for (int i = 0; i < 8; i++) As[ml + i * 16][kl] = ra[i];
#pragma unroll
        for (int i = 0; i < 4; i++) Bs[skk[i]][snn[i]] = rb[i];
        __syncthreads();

        int kn = k0 + KC;
        if (kn < K) {
#pragma unroll
            for (int i = 0; i < 8; i++) ra[i] = arow[i][kn];
#pragma unroll
            for (int i = 0; i < 4; i++)
                rb[i] = (BN == 0) ? brow[i][kn] : brow[i][(long long)kn * ldb];
        }

#pragma unroll
        for (int k = 0; k < KC; k++) {
            float4 b = *(const float4*)&Bs[k][tx * 4];
            unsigned long long b01 = pack2(b.x, b.y);
            unsigned long long b23 = pack2(b.z, b.w);
#pragma unroll
            for (int i = 0; i < 8; i++) {
                unsigned long long a2 = packdup(As[ty * 8 + i][k]);
                acc01[i] = fma2(a2, b01, acc01[i]);
                acc23[i] = fma2(a2, b23, acc23[i]);
            }
        }
        __syncthreads();
    }

#pragma unroll
    for (int i = 0; i < 8; i++) {
        int m = m0 + ty * 8 + i;
        long long base = (long long)m * ldc + n0 + tx * 4;
        float v0, v1, v2, v3;
        unpack2(acc01[i], v0, v1);
        unpack2(acc23[i], v2, v3);
        if (mode == 1) {
            v0 = fmaxf(v0 + Ep[base + 0], 0.f);
            v1 = fmaxf(v1 + Ep[base + 1], 0.f);
            v2 = fmaxf(v2 + Ep[base + 2], 0.f);
            v3 = fmaxf(v3 + Ep[base + 3], 0.f);
        }
        C[base + 0] = v0; C[base + 1] = v1; C[base + 2] = v2; C[base + 3] = v3;
    }
}

// ---------------- fused attention, layer 1 ----------------
// per node n: gather h2[10][256], scores[f][h] = 0.125 * h2[f].u1[n,h],
// softmax over f, m1[n,h,e] = sum_f attn * h2[f][e]
__global__ __launch_bounds__(256) void attn1_kernel(const float* __restrict__ emb) {
    __shared__ float sh2[FAN_2][EMB];
    __shared__ float shu[HEADS * EMB];
    __shared__ float sc[FAN_2][HEADS];
    __shared__ float at[FAN_2][HEADS];
    int n = blockIdx.x, tid = threadIdx.x;

    for (int i = tid; i < FAN_2 * EMB; i += 256) {
        int f = i >> 8, e = i & 255;
        sh2[f][e] = emb[(long long)g_nbr2[n * FAN_2 + f] * EMB + e];
    }
    const float* up = g_u1 + (long long)n * HEADS * EMB;
    for (int i = tid; i < HEADS * EMB; i += 256) shu[i] = up[i];
    __syncthreads();

    int w = tid >> 5, l = tid & 31;  // warp w == head w
    for (int f = 0; f < FAN_2; f++) {
        float p = 0.f;
        for (int e = l; e < EMB; e += 32) p += sh2[f][e] * shu[w * EMB + e];
#pragma unroll
        for (int o = 16; o; o >>= 1) p += __shfl_xor_sync(0xffffffffu, p, o);
        if (l == 0) sc[f][w] = p * 0.125f;
    }
    __syncthreads();

    if (tid < HEADS) {
        float mx = -1e30f;
        for (int f = 0; f < FAN_2; f++) mx = fmaxf(mx, sc[f][tid]);
        float ex[FAN_2]; float s = 0.f;
        for (int f = 0; f < FAN_2; f++) { ex[f] = expf(sc[f][tid] - mx); s += ex[f]; }
        float inv = 1.f / s;
        for (int f = 0; f < FAN_2; f++) at[f][tid] = ex[f] * inv;
    }
    __syncthreads();

    float* mp = g_m1 + (long long)n * HEADS * EMB;
    for (int i = tid; i < HEADS * EMB; i += 256) {
        int h = i >> 8, e = i & 255;
        float s = 0.f;
#pragma unroll
        for (int f = 0; f < FAN_2; f++) s += at[f][h] * sh2[f][e];
        mp[i] = s;
    }
}

// ---------------- fused attention, layer 2 ----------------
__global__ __launch_bounds__(256) void attn2_kernel() {
    __shared__ float sh1[FAN_1][HID];       // 30720 B
    __shared__ float shu[HEADS * HID];      // 16384 B
    __shared__ float sc[FAN_1][HEADS];
    __shared__ float at[FAN_1][HEADS];
    int b = blockIdx.x, tid = threadIdx.x;

    const float* hp = g_h1 + (long long)b * FAN_1 * HID;  // 15 contiguous rows
    for (int i = tid; i < FAN_1 * HID; i += 256) {
        int f = i >> 9, e = i & 511;
        sh1[f][e] = hp[i];
    }
    const float* up = g_u2 + (long long)b * HEADS * HID;
    for (int i = tid; i < HEADS * HID; i += 256) shu[i] = up[i];
    __syncthreads();

    int w = tid >> 5, l = tid & 31;
    for (int f = 0; f < FAN_1; f++) {
        float p = 0.f;
        for (int e = l; e < HID; e += 32) p += sh1[f][e] * shu[w * HID + e];
#pragma unroll
        for (int o = 16; o; o >>= 1) p += __shfl_xor_sync(0xffffffffu, p, o);
        if (l == 0) sc[f][w] = p * 0.125f;
    }
    __syncthreads();

    if (tid < HEADS) {
        float mx = -1e30f;
        for (int f = 0; f < FAN_1; f++) mx = fmaxf(mx, sc[f][tid]);
        float ex[FAN_1]; float s = 0.f;
        for (int f = 0; f < FAN_1; f++) { ex[f] = expf(sc[f][tid] - mx); s += ex[f]; }
        float inv = 1.f / s;
        for (int f = 0; f < FAN_1; f++) at[f][tid] = ex[f] * inv;
    }
    __syncthreads();

    float* mp = g_m2 + (long long)b * HEADS * HID;
    for (int i = tid; i < HEADS * HID; i += 256) {
        int h = i >> 9, e = i & 511;
        float s = 0.f;
#pragma unroll
        for (int f = 0; f < FAN_1; f++) s += at[f][h] * sh1[f][e];
        mp[i] = s;
    }
}

// ---------------- host ----------------
extern "C" void kernel_launch(void* const* d_in, const int* in_sizes, int n_in,
                              void* d_out, int out_size) {
    const void* seeds = d_in[0];
    const void* nbr1  = d_in[1];
    const void* nbr2  = d_in[2];
    const float* emb = (const float*)d_in[3];
    const float* Wq1 = (const float*)d_in[4];
    const float* Wk1 = (const float*)d_in[5];
    const float* Wv1 = (const float*)d_in[6];
    const float* Ws1 = (const float*)d_in[7];
    const float* Wq2 = (const float*)d_in[8];
    const float* Wk2 = (const float*)d_in[9];
    const float* Wv2 = (const float*)d_in[10];
    const float* Ws2 = (const float*)d_in[11];
    float* out = (float*)d_out;

    void *q1, *s1, *u1, *m1, *h1, *q2, *s2, *u2, *m2, *iseeds, *inbr1;
    cudaGetSymbolAddress(&q1, g_q1);
    cudaGetSymbolAddress(&s1, g_s1);
    cudaGetSymbolAddress(&u1, g_u1);
    cudaGetSymbolAddress(&m1, g_m1);
    cudaGetSymbolAddress(&h1, g_h1);
    cudaGetSymbolAddress(&q2, g_q2);
    cudaGetSymbolAddress(&s2, g_s2);
    cudaGetSymbolAddress(&u2, g_u2);
    cudaGetSymbolAddress(&m2, g_m2);
    cudaGetSymbolAddress(&iseeds, g_seeds);
    cudaGetSymbolAddress(&inbr1, g_nbr1);

    convert_idx<<<600, 256>>>(seeds, nbr1, nbr2);

    // layer 1: q1 = gather(emb,nbr1) @ Wq1^T ; s1 likewise with Ws1
    gemm_kernel<0><<<dim3(HID / 64, N1 / 128, 1), 256>>>(
        (float*)q1, HID, 0, nullptr, 0, 0,
        emb, EMB, 0, (const int*)inbr1, Wq1, EMB, 0, EMB);
    gemm_kernel<0><<<dim3(HID / 64, N1 / 128, 1), 256>>>(
        (float*)s1, HID, 0, nullptr, 0, 0,
        emb, EMB, 0, (const int*)inbr1, Ws1, EMB, 0, EMB);

    // u1[n,h,:] = q1[n,h*64..] @ Wk1[h*64.., :]   (per-head GEMM over z)
    gemm_kernel<1><<<dim3(EMB / 64, N1 / 128, HEADS), 256>>>(
        (float*)u1, HEADS * EMB, EMB, nullptr, 0, 0,
        (const float*)q1, HID, HD, nullptr, Wk1, EMB, (long long)HD * EMB, HD);

    attn1_kernel<<<N1, 256>>>(emb);

    // h1 = relu(s1 + m1 @ Wv1_h^T)
    gemm_kernel<0><<<dim3(1, N1 / 128, HEADS), 256>>>(
        (float*)h1, HID, HD, (const float*)s1, HD, 1,
        (const float*)m1, HEADS * EMB, EMB, nullptr,
        Wv1, EMB, (long long)HD * EMB, EMB);

    // layer 2
    gemm_kernel<0><<<dim3(HID / 64, NB_B / 128, 1), 256>>>(
        (float*)q2, HID, 0, nullptr, 0, 0,
        emb, EMB, 0, (const int*)iseeds, Wq2, EMB, 0, EMB);
    gemm_kernel<0><<<dim3(HID / 64, NB_B / 128, 1), 256>>>(
        (float*)s2, HID, 0, nullptr, 0, 0,
        emb, EMB, 0, (const int*)iseeds, Ws2, EMB, 0, EMB);

    gemm_kernel<1><<<dim3(HID / 64, NB_B / 128, HEADS), 256>>>(
        (float*)u2, HEADS * HID, HID, nullptr, 0, 0,
        (const float*)q2, HID, HD, nullptr, Wk2, HID, (long long)HD * HID, HD);

    attn2_kernel<<<NB_B, 256>>>();

    // out = relu(s2 + m2 @ Wv2_h^T)
    gemm_kernel<0><<<dim3(1, NB_B / 128, HEADS), 256>>>(
        out, HID, HD, (const float*)s2, HD, 1,
        (const float*)m2, HEADS * HID, HID, nullptr,
        Wv2, HID, (long long)HD * HID, HID);
}